// round 2
// baseline (speedup 1.0000x reference)
#include <cuda_runtime.h>
#include <cuda_bf16.h>

// Haar wavelet 2x2 transform.
// Input:  x[B=8, C=64, H=512, W=512] fp32
// Output: out[B=8, 4*C=256, H/2=256, W/2=256] fp32
// out channel = 4*c + band, band in {ll, lh, hl, hh}.
//
// Each thread: 8 output columns. Reads 2 rows x 64B (4x float4 per row, MLP=8),
// writes 2x float4 to each of 4 output planes. A warp covers exactly two full
// input rows (2 KiB each) and four full output rows (1 KiB each).

#define B_ 8
#define C_ 64
#define H_ 512
#define W_ 512
#define H2_ (H_ / 2)
#define W2_ (W_ / 2)
#define NCOLS 8                       // output columns per thread
#define WGROUPS (W2_ / NCOLS)         // 32 column-groups per output row

__global__ __launch_bounds__(256)
void haar_kernel(const float* __restrict__ x, float* __restrict__ out) {
    long long idx = (long long)blockIdx.x * blockDim.x + threadIdx.x;
    // total = B*C*H2*WGROUPS = 8*64*256*32 = 4,194,304
    int wg = (int)(idx & (WGROUPS - 1));
    long long t = idx >> 5;           // / WGROUPS
    int h2 = (int)(t & (H2_ - 1));
    t >>= 8;                          // / H2_
    int c = (int)(t & (C_ - 1));
    int b = (int)(t >> 6);            // / C_

    const long long in_plane = (long long)(b * C_ + c) * (H_ * W_);
    const long long in_row0 = in_plane + (long long)(2 * h2) * W_ + (long long)(2 * NCOLS) * wg;
    const long long in_row1 = in_row0 + W_;

    // 16 consecutive floats per row = 4x float4; streaming (evict-first) loads.
    float4 r0[4], r1[4];
    #pragma unroll
    for (int i = 0; i < 4; ++i)
        r0[i] = __ldcs(reinterpret_cast<const float4*>(x + in_row0) + i);
    #pragma unroll
    for (int i = 0; i < 4; ++i)
        r1[i] = __ldcs(reinterpret_cast<const float4*>(x + in_row1) + i);

    float4 ll[2], lh[2], hl[2], hh[2];
    #pragma unroll
    for (int g = 0; g < 2; ++g) {     // two float4 output groups
        float* llp = &ll[g].x; float* lhp = &lh[g].x;
        float* hlp = &hl[g].x; float* hhp = &hh[g].x;
        #pragma unroll
        for (int j = 0; j < 4; ++j) { // output col within group
            int k = g * 8 + j * 2;    // even input col index within the 16
            const float* f0 = reinterpret_cast<const float*>(r0);
            const float* f1 = reinterpret_cast<const float*>(r1);
            float x00 = f0[k],   x01 = f0[k + 1];
            float x10 = f1[k],   x11 = f1[k + 1];
            float s0 = x00 + x01;
            float s1 = x10 + x11;
            float d0 = x01 - x00;
            float d1 = x11 - x10;
            llp[j] = 0.5f * (s0 + s1);
            lhp[j] = 0.5f * (s1 - s0);
            hlp[j] = 0.5f * (d0 + d1);
            hhp[j] = 0.5f * (d1 - d0);
        }
    }

    const long long out_base =
        ((long long)(b * (4 * C_) + 4 * c) * H2_ + h2) * W2_ + (long long)NCOLS * wg;
    const long long ps = (long long)H2_ * W2_;  // plane stride

    float4* o0 = reinterpret_cast<float4*>(out + out_base);
    float4* o1 = reinterpret_cast<float4*>(out + out_base + ps);
    float4* o2 = reinterpret_cast<float4*>(out + out_base + 2 * ps);
    float4* o3 = reinterpret_cast<float4*>(out + out_base + 3 * ps);
    __stcs(o0,     ll[0]); __stcs(o0 + 1, ll[1]);
    __stcs(o1,     lh[0]); __stcs(o1 + 1, lh[1]);
    __stcs(o2,     hl[0]); __stcs(o2 + 1, hl[1]);
    __stcs(o3,     hh[0]); __stcs(o3 + 1, hh[1]);
}

extern "C" void kernel_launch(void* const* d_in, const int* in_sizes, int n_in,
                              void* d_out, int out_size) {
    const float* x = (const float*)d_in[0];
    float* out = (float*)d_out;
    const long long total_threads = (long long)B_ * C_ * H2_ * WGROUPS; // 4,194,304
    const int threads = 256;
    const int blocks = (int)(total_threads / threads);                  // 16384
    haar_kernel<<<blocks, threads>>>(x, out);
}